// round 6
// baseline (speedup 1.0000x reference)
#include <cuda_runtime.h>
#include <cuda_bf16.h>
#include <cstdint>

// Problem constants
#define LDm   16384
#define LUm   65536
#define NNm   8
#define DIN   256
#define DOUT  128
#define M_ROWS (LDm * NNm)            // 131072 MLP rows
#define OUT_ROWS ((long)LUm * NNm)    // 524288 output rows

// Arch-specific (sm_103a/sm_100a) pass?
#if defined(__CUDA_ARCH__) && (defined(__CUDA_ARCH_FEAT_SM103_ALL) || \
    defined(__CUDA_ARCH_FEAT_SM100_ALL) || \
    (defined(__CUDA_ARCH_SPECIFIC__) && (__CUDA_ARCH_SPECIFIC__ >= 1000)))
#define HAS_TCGEN05 1
#else
#define HAS_TCGEN05 0
#endif

// Scratch: h = relu(x@W1+b1)@W2+b2  [LD, N, D_OUT] (64 MB), 32B-aligned rows
__device__ __align__(128) float g_h[(size_t)M_ROWS * DOUT];
// Precomputed bf16 hi/lo splits of W1^T, W2^T (B operands, N x K, K-major)
__device__ __align__(16) __nv_bfloat16 g_w1t_hi[DOUT * DIN];
__device__ __align__(16) __nv_bfloat16 g_w1t_lo[DOUT * DIN];
__device__ __align__(16) __nv_bfloat16 g_w2t_hi[DOUT * DOUT];
__device__ __align__(16) __nv_bfloat16 g_w2t_lo[DOUT * DOUT];

// SMEM layout (tcgen05 path): A = 256 rows x 128B per buffer
#define SM_AHI 1024                      // 32768 bytes
#define SM_ALO (SM_AHI + 32768)          // 33792
#define SM_BHI (SM_ALO + 32768)          // 66560
#define SM_BLO (SM_BHI + 16384)          // 82944
#define SM_B1  (SM_BLO + 16384)          // 99328
#define SM_B2  (SM_B1 + 512)             // 99840
#define SMEM_TOTAL (SM_B2 + 512)         // 100352

// ---------------------------------------------------------------------------
// Pre-kernel: split W1^T / W2^T into bf16 hi/lo
// ---------------------------------------------------------------------------
__global__ void wsplit_kernel(const float* __restrict__ W1,
                              const float* __restrict__ W2)
{
    int t = blockIdx.x * blockDim.x + threadIdx.x;
    if (t < DOUT * DIN) {                   // W1^T: [n][k], n<128, k<256
        int n = t >> 8, k = t & 255;
        float x = W1[k * DOUT + n];
        uint32_t b = __float_as_uint(x);
        float hf = __uint_as_float(b & 0xFFFF0000u);
        g_w1t_hi[t] = __ushort_as_bfloat16((unsigned short)(b >> 16));
        g_w1t_lo[t] = __float2bfloat16(x - hf);
    } else {
        int t2 = t - DOUT * DIN;
        if (t2 < DOUT * DOUT) {             // W2^T: [n][k], n<128, k<128
            int n = t2 >> 7, k = t2 & 127;
            float x = W2[k * DOUT + n];
            uint32_t b = __float_as_uint(x);
            float hf = __uint_as_float(b & 0xFFFF0000u);
            g_w2t_hi[t2] = __ushort_as_bfloat16((unsigned short)(b >> 16));
            g_w2t_lo[t2] = __float2bfloat16(x - hf);
        }
    }
}

#if HAS_TCGEN05
// ---------------------------------------------------------------------------
// PTX helpers
// ---------------------------------------------------------------------------
__device__ __forceinline__ uint32_t smem_u32(const void* p) {
    uint32_t a;
    asm("{ .reg .u64 t; cvta.to.shared.u64 t, %1; cvt.u32.u64 %0, t; }"
        : "=r"(a) : "l"(p));
    return a;
}
__device__ __forceinline__ uint32_t elect_one() {
    uint32_t p;
    asm volatile("{ .reg .pred p; elect.sync _|p, 0xFFFFFFFF; selp.b32 %0,1,0,p; }"
                 : "=r"(p));
    return p;
}
#define TCG_ALLOC(sm, n)  asm volatile("tcgen05.alloc.cta_group::1.sync.aligned.shared::cta.b32 [%0], %1;" :: "r"(sm), "r"((uint32_t)(n)) : "memory")
#define TCG_DEALLOC(t, n) asm volatile("tcgen05.dealloc.cta_group::1.sync.aligned.b32 %0, %1;" :: "r"(t), "r"((uint32_t)(n)))
#define TCG_RELINQ()      asm volatile("tcgen05.relinquish_alloc_permit.cta_group::1.sync.aligned;")
#define TCG_COMMIT(mb)    asm volatile("tcgen05.commit.cta_group::1.mbarrier::arrive::one.shared::cluster.b64 [%0];" :: "r"(mb) : "memory")
#define TCG_WAIT_LD()     asm volatile("tcgen05.wait::ld.sync.aligned;" ::: "memory")
#define TCG_FENCE_BEFORE() asm volatile("tcgen05.fence::before_thread_sync;" ::: "memory")
#define TCG_FENCE_AFTER()  asm volatile("tcgen05.fence::after_thread_sync;" ::: "memory")
#define FENCE_ASYNC_SHARED() asm volatile("fence.proxy.async.shared::cta;" ::: "memory")
#define MBAR_INIT(mb, c)  asm volatile("mbarrier.init.shared.b64 [%0], %1;" :: "r"(mb), "r"((uint32_t)(c)) : "memory")
#define MBAR_INVAL(mb)    asm volatile("mbarrier.inval.shared.b64 [%0];" :: "r"(mb) : "memory")

__device__ __forceinline__ void mbar_wait(uint32_t mb, uint32_t parity) {
    asm volatile(
        "{\n\t.reg .pred P1;\n\t"
        "WAIT_LOOP_%=:\n\t"
        "mbarrier.try_wait.parity.acquire.cta.shared::cta.b64 P1, [%0], %1, 0x989680;\n\t"
        "@P1 bra.uni WAIT_DONE_%=;\n\t"
        "bra.uni WAIT_LOOP_%=;\n\t"
        "WAIT_DONE_%=:\n\t}"
        :: "r"(mb), "r"(parity) : "memory");
}

__device__ __forceinline__ void mma_ss(uint32_t d, uint64_t ad, uint64_t bd,
                                       uint32_t idesc, uint32_t en) {
    asm volatile(
        "{\n\t.reg .pred p;\n\tsetp.ne.u32 p, %4, 0;\n\t"
        "tcgen05.mma.cta_group::1.kind::f16 [%0], %1, %2, %3, {%5,%5,%5,%5}, p;\n\t}"
        :: "r"(d), "l"(ad), "l"(bd), "r"(idesc), "r"(en), "r"(0u) : "memory");
}

#define LDTM_X16(r, a) \
    asm volatile("tcgen05.ld.sync.aligned.32x32b.x16.b32 " \
        "{%0,%1,%2,%3,%4,%5,%6,%7,%8,%9,%10,%11,%12,%13,%14,%15}, [%16];" \
        : "=r"((r)[0]),"=r"((r)[1]),"=r"((r)[2]),"=r"((r)[3]), \
          "=r"((r)[4]),"=r"((r)[5]),"=r"((r)[6]),"=r"((r)[7]), \
          "=r"((r)[8]),"=r"((r)[9]),"=r"((r)[10]),"=r"((r)[11]), \
          "=r"((r)[12]),"=r"((r)[13]),"=r"((r)[14]),"=r"((r)[15]) : "r"(a))

#define LDTM_X32(r, a) \
    asm volatile("tcgen05.ld.sync.aligned.32x32b.x32.b32 " \
        "{%0,%1,%2,%3,%4,%5,%6,%7,%8,%9,%10,%11,%12,%13,%14,%15," \
        "%16,%17,%18,%19,%20,%21,%22,%23,%24,%25,%26,%27,%28,%29,%30,%31}, [%32];" \
        : "=r"((r)[0]),"=r"((r)[1]),"=r"((r)[2]),"=r"((r)[3]), \
          "=r"((r)[4]),"=r"((r)[5]),"=r"((r)[6]),"=r"((r)[7]), \
          "=r"((r)[8]),"=r"((r)[9]),"=r"((r)[10]),"=r"((r)[11]), \
          "=r"((r)[12]),"=r"((r)[13]),"=r"((r)[14]),"=r"((r)[15]), \
          "=r"((r)[16]),"=r"((r)[17]),"=r"((r)[18]),"=r"((r)[19]), \
          "=r"((r)[20]),"=r"((r)[21]),"=r"((r)[22]),"=r"((r)[23]), \
          "=r"((r)[24]),"=r"((r)[25]),"=r"((r)[26]),"=r"((r)[27]), \
          "=r"((r)[28]),"=r"((r)[29]),"=r"((r)[30]),"=r"((r)[31]) : "r"(a))

__device__ __forceinline__ uint64_t mk_desc(uint32_t addr) {
    return ((uint64_t)2 << 61) | ((uint64_t)1 << 46) | ((uint64_t)64 << 32) |
           ((uint64_t)1 << 16) | (uint64_t)((addr >> 4) & 0x3FFF);
}
#endif // HAS_TCGEN05

#define SWZ(o) ((o) ^ (((o) >> 3) & 0x70))

// Truncation split: hi = top-16-bits of fp32, lo = rn_bf16(x - hi)
__device__ __forceinline__ void split2(float x0, float x1, uint32_t& hi, uint32_t& lo) {
    uint32_t b0 = __float_as_uint(x0), b1 = __float_as_uint(x1);
    hi = __byte_perm(b0, b1, 0x7632);
    float l0 = x0 - __uint_as_float(b0 & 0xFFFF0000u);
    float l1 = x1 - __uint_as_float(b1 & 0xFFFF0000u);
    asm("cvt.rn.bf16x2.f32 %0, %1, %2;" : "=r"(lo) : "f"(l1), "f"(l0));
}

// 256-bit evict_last global load (8 floats) — evict_last requires 256-bit width
__device__ __forceinline__ void ldg_evl8(const float* p, float* v) {
    uint64_t a, b, c, d;
    asm volatile("ld.global.nc.L2::evict_last.v4.b64 {%0,%1,%2,%3}, [%4];"
        : "=l"(a), "=l"(b), "=l"(c), "=l"(d) : "l"(p));
    v[0] = __uint_as_float((uint32_t)a); v[1] = __uint_as_float((uint32_t)(a >> 32));
    v[2] = __uint_as_float((uint32_t)b); v[3] = __uint_as_float((uint32_t)(b >> 32));
    v[4] = __uint_as_float((uint32_t)c); v[5] = __uint_as_float((uint32_t)(c >> 32));
    v[6] = __uint_as_float((uint32_t)d); v[7] = __uint_as_float((uint32_t)(d >> 32));
}
// 256-bit evict_last global store (8 floats)
__device__ __forceinline__ void stg_evl8(float* p, const float* v) {
    uint64_t a = (uint64_t)__float_as_uint(v[0]) | ((uint64_t)__float_as_uint(v[1]) << 32);
    uint64_t b = (uint64_t)__float_as_uint(v[2]) | ((uint64_t)__float_as_uint(v[3]) << 32);
    uint64_t c = (uint64_t)__float_as_uint(v[4]) | ((uint64_t)__float_as_uint(v[5]) << 32);
    uint64_t d = (uint64_t)__float_as_uint(v[6]) | ((uint64_t)__float_as_uint(v[7]) << 32);
    asm volatile("st.global.L2::evict_last.v4.b64 [%0], {%1,%2,%3,%4};"
        :: "l"(p), "l"(a), "l"(b), "l"(c), "l"(d) : "memory");
}

// ---------------------------------------------------------------------------
// MLP kernel: 256 rows per CTA (two M=128 MMA halves), grid=512, 256 threads.
// TMEM cols: D1h0=0..127, D1h1=128..255, D2h0=256..383, D2h1=384..511.
// ---------------------------------------------------------------------------
__global__ __launch_bounds__(256, 2)
void mlp_kernel(const float* __restrict__ X,
                const float* __restrict__ W1,
                const float* __restrict__ b1,
                const float* __restrict__ W2,
                const float* __restrict__ b2)
{
    extern __shared__ char smem[];
#if HAS_TCGEN05
    const uint32_t sb  = smem_u32(smem);
    const int tid = threadIdx.x, wid = tid >> 5, lid = tid & 31;
    const long rowBase = (long)blockIdx.x * 256;

    float* b1s = (float*)(smem + SM_B1);
    float* b2s = (float*)(smem + SM_B2);

    if (wid == 0) { TCG_ALLOC(sb + 0, 512); TCG_RELINQ(); }
    if (tid == 0) MBAR_INIT(sb + 8, 1);
    if (tid < 128) { b1s[tid] = b1[tid]; b2s[tid] = b2[tid]; }
    __syncthreads();

    uint32_t tmem;
    asm volatile("ld.shared.b32 %0, [%1];" : "=r"(tmem) : "r"(sb + 0));

    const uint32_t idesc = (1u << 4) | (1u << 7) | (1u << 10) |
                           ((DOUT / 8) << 17) | ((128 / 16) << 24);
    const uint64_t adhi0 = mk_desc(sb + SM_AHI);
    const uint64_t adhi1 = mk_desc(sb + SM_AHI + 16384);
    const uint64_t adlo0 = mk_desc(sb + SM_ALO);
    const uint64_t adlo1 = mk_desc(sb + SM_ALO + 16384);
    const uint64_t bdhi  = mk_desc(sb + SM_BHI);
    const uint64_t bdlo  = mk_desc(sb + SM_BLO);

    uint32_t parity = 0;

    // ================= GEMM1: 4 K-chunks of 64 =================
    for (int kb = 0; kb < 4; kb++) {
        const float* Xc = X + rowBase * DIN + kb * 64;
#pragma unroll
        for (int it = 0; it < 8; it++) {
            int f  = it * 256 + tid;     // 0..2047
            int r  = f >> 3;             // row 0..255
            int c8 = f & 7;
            const float4* src = (const float4*)(Xc + (size_t)r * DIN + c8 * 8);
            float4 va = src[0], vb = src[1];
            uint32_t h0, l0, h1, l1, h2, l2, h3, l3;
            split2(va.x, va.y, h0, l0);
            split2(va.z, va.w, h1, l1);
            split2(vb.x, vb.y, h2, l2);
            split2(vb.z, vb.w, h3, l3);
            uint32_t off = SWZ((uint32_t)(r * 128 + c8 * 16));
            *(uint4*)(smem + SM_AHI + off) = make_uint4(h0, h1, h2, h3);
            *(uint4*)(smem + SM_ALO + off) = make_uint4(l0, l1, l2, l3);
        }
#pragma unroll
        for (int it = 0; it < 8; it++) {
            int f = it * 256 + tid;
            int g = f & 1023;
            int n = g >> 3, c16 = g & 7;
            const __nv_bfloat16* wsrc = (f < 1024) ? g_w1t_hi : g_w1t_lo;
            uint4 v = *(const uint4*)(wsrc + (size_t)n * DIN + kb * 64 + c16 * 8);
            uint32_t dst = ((f < 1024) ? SM_BHI : SM_BLO) + SWZ((uint32_t)(n * 128 + c16 * 16));
            *(uint4*)(smem + dst) = v;
        }
        __syncthreads();

        if (wid == 0) {
            FENCE_ASYNC_SHARED();
            if (elect_one()) {
#pragma unroll
                for (int half = 0; half < 2; half++) {
                    uint32_t d = tmem + half * 128;
                    uint64_t ah = half ? adhi1 : adhi0;
                    uint64_t al = half ? adlo1 : adlo0;
#pragma unroll
                    for (int ks = 0; ks < 4; ks++)
                        mma_ss(d, ah + ks * 2, bdhi + ks * 2, idesc, (kb > 0) || (ks > 0));
#pragma unroll
                    for (int ks = 0; ks < 4; ks++)
                        mma_ss(d, ah + ks * 2, bdlo + ks * 2, idesc, 1);
#pragma unroll
                    for (int ks = 0; ks < 4; ks++)
                        mma_ss(d, al + ks * 2, bdhi + ks * 2, idesc, 1);
                }
                TCG_COMMIT(sb + 8);
            }
        }
        mbar_wait(sb + 8, parity); parity ^= 1;
        TCG_FENCE_AFTER();
    }

    // ================= GEMM2: 2 K-chunks of 64 =================
    const int half = wid >> 2;                 // 0: warps 0-3, 1: warps 4-7
    const int subrow = (wid & 3) * 32 + lid;   // TMEM lane row 0..127
    for (int c2 = 0; c2 < 2; c2++) {
        {
            int rowA = half * 128 + subrow;
            uint32_t dbase = tmem + half * 128 + c2 * 64;
#pragma unroll
            for (int part = 0; part < 4; part++) {
                uint32_t r16[16];
                LDTM_X16(r16, dbase + part * 16);
                TCG_WAIT_LD();
#pragma unroll
                for (int grp = 0; grp < 2; grp++) {
                    uint32_t hs[4], ls[4];
#pragma unroll
                    for (int q = 0; q < 4; q++) {
                        int c = grp * 8 + q * 2;
                        float x0 = __uint_as_float(r16[c])     + b1s[c2 * 64 + part * 16 + c];
                        float x1 = __uint_as_float(r16[c + 1]) + b1s[c2 * 64 + part * 16 + c + 1];
                        x0 = fmaxf(x0, 0.f);
                        x1 = fmaxf(x1, 0.f);
                        split2(x0, x1, hs[q], ls[q]);
                    }
                    uint32_t off = SWZ((uint32_t)(rowA * 128 + (part * 16 + grp * 8) * 2));
                    *(uint4*)(smem + SM_AHI + off) = make_uint4(hs[0], hs[1], hs[2], hs[3]);
                    *(uint4*)(smem + SM_ALO + off) = make_uint4(ls[0], ls[1], ls[2], ls[3]);
                }
            }
            TCG_FENCE_BEFORE();
        }
#pragma unroll
        for (int it = 0; it < 8; it++) {
            int f = it * 256 + tid;
            int g = f & 1023;
            int n = g >> 3, c16 = g & 7;
            const __nv_bfloat16* wsrc = (f < 1024) ? g_w2t_hi : g_w2t_lo;
            uint4 v = *(const uint4*)(wsrc + (size_t)n * DOUT + c2 * 64 + c16 * 8);
            uint32_t dst = ((f < 1024) ? SM_BHI : SM_BLO) + SWZ((uint32_t)(n * 128 + c16 * 16));
            *(uint4*)(smem + dst) = v;
        }
        __syncthreads();

        if (wid == 0) {
            FENCE_ASYNC_SHARED();
            if (elect_one()) {
#pragma unroll
                for (int h2 = 0; h2 < 2; h2++) {
                    uint32_t d = tmem + 256 + h2 * 128;
                    uint64_t ah = h2 ? adhi1 : adhi0;
                    uint64_t al = h2 ? adlo1 : adlo0;
#pragma unroll
                    for (int ks = 0; ks < 4; ks++)
                        mma_ss(d, ah + ks * 2, bdhi + ks * 2, idesc, (c2 > 0) || (ks > 0));
#pragma unroll
                    for (int ks = 0; ks < 4; ks++)
                        mma_ss(d, ah + ks * 2, bdlo + ks * 2, idesc, 1);
#pragma unroll
                    for (int ks = 0; ks < 4; ks++)
                        mma_ss(d, al + ks * 2, bdhi + ks * 2, idesc, 1);
                }
                TCG_COMMIT(sb + 8);
            }
        }
        mbar_wait(sb + 8, parity); parity ^= 1;
        TCG_FENCE_AFTER();
    }

    // ================= Epilogue: D2 + b2 -> g_h (256-bit evict_last st) ======
    {
        float* dst = g_h + (size_t)(rowBase + half * 128 + subrow) * DOUT;
        uint32_t dbase = tmem + 256 + half * 128;
#pragma unroll
        for (int grp = 0; grp < 4; grp++) {
            uint32_t r32[32];
            LDTM_X32(r32, dbase + grp * 32);
            TCG_WAIT_LD();
            float o[32];
#pragma unroll
            for (int c = 0; c < 32; c++)
                o[c] = __uint_as_float(r32[c]) + b2s[grp * 32 + c];
#pragma unroll
            for (int q = 0; q < 4; q++)
                stg_evl8(dst + grp * 32 + q * 8, o + q * 8);
        }
        TCG_FENCE_BEFORE();
    }
    __syncthreads();
    if (tid == 0) MBAR_INVAL(sb + 8);
    __syncthreads();
    if (wid == 0) TCG_DEALLOC(tmem, 512);

#else  // ===================== fp32 FFMA fallback (4 x 64-row halves) ========
    float (*xs)[68]   = (float (*)[68])(smem);
    float (*ws)[128]  = (float (*)[128])(smem + 32 * 68 * 4);
    float (*h1T)[68]  = (float (*)[68])(smem + 32 * 68 * 4 + 32 * 128 * 4);

    const int tid = threadIdx.x;
    const int tr  = tid >> 5;
    const int tc  = tid & 31;

    for (int quarter = 0; quarter < 4; quarter++) {
        const long rowBase = (long)blockIdx.x * 256 + quarter * 64;
        float acc[8][4];
#pragma unroll
        for (int r = 0; r < 8; r++)
#pragma unroll
            for (int c = 0; c < 4; c++) acc[r][c] = 0.f;

        for (int kb = 0; kb < DIN; kb += 32) {
#pragma unroll
            for (int it = 0; it < 2; it++) {
                int f = tid + it * 256;
                int r  = f >> 3;
                int k4 = f & 7;
                float4 v = *(const float4*)(X + (rowBase + r) * DIN + kb + k4 * 4);
                xs[k4 * 4 + 0][r] = v.x;
                xs[k4 * 4 + 1][r] = v.y;
                xs[k4 * 4 + 2][r] = v.z;
                xs[k4 * 4 + 3][r] = v.w;
            }
#pragma unroll
            for (int it = 0; it < 4; it++) {
                int f  = tid + it * 256;
                int kr = f >> 5;
                int c4 = f & 31;
                *(float4*)&ws[kr][c4 * 4] =
                    *(const float4*)(W1 + (size_t)(kb + kr) * DOUT + c4 * 4);
            }
            __syncthreads();
#pragma unroll
            for (int kk = 0; kk < 32; kk++) {
                float4 xa = *(float4*)&xs[kk][tr * 8];
                float4 xb = *(float4*)&xs[kk][tr * 8 + 4];
                float4 w  = *(float4*)&ws[kk][tc * 4];
                float xr[8] = {xa.x, xa.y, xa.z, xa.w, xb.x, xb.y, xb.z, xb.w};
                float wr[4] = {w.x, w.y, w.z, w.w};
#pragma unroll
                for (int r = 0; r < 8; r++)
#pragma unroll
                    for (int c = 0; c < 4; c++)
                        acc[r][c] = fmaf(xr[r], wr[c], acc[r][c]);
            }
            __syncthreads();
        }
        {
            float bb[4];
#pragma unroll
            for (int c = 0; c < 4; c++) bb[c] = b1[tc * 4 + c];
#pragma unroll
            for (int r = 0; r < 8; r++)
#pragma unroll
                for (int c = 0; c < 4; c++) {
                    float v = acc[r][c] + bb[c];
                    h1T[tc * 4 + c][tr * 8 + r] = fmaxf(v, 0.f);
                    acc[r][c] = 0.f;
                }
        }
        __syncthreads();

        for (int kb = 0; kb < DOUT; kb += 32) {
#pragma unroll
            for (int it = 0; it < 4; it++) {
                int f  = tid + it * 256;
                int kr = f >> 5;
                int c4 = f & 31;
                *(float4*)&ws[kr][c4 * 4] =
                    *(const float4*)(W2 + (size_t)(kb + kr) * DOUT + c4 * 4);
            }
            __syncthreads();
#pragma unroll
            for (int kk = 0; kk < 32; kk++) {
                float4 xa = *(float4*)&h1T[kb + kk][tr * 8];
                float4 xb = *(float4*)&h1T[kb + kk][tr * 8 + 4];
                float4 w  = *(float4*)&ws[kk][tc * 4];
                float xr[8] = {xa.x, xa.y, xa.z, xa.w, xb.x, xb.y, xb.z, xb.w};
                float wr[4] = {w.x, w.y, w.z, w.w};
#pragma unroll
                for (int r = 0; r < 8; r++)
#pragma unroll
                    for (int c = 0; c < 4; c++)
                        acc[r][c] = fmaf(xr[r], wr[c], acc[r][c]);
            }
            __syncthreads();
        }
        {
            float bb[4];
#pragma unroll
            for (int c = 0; c < 4; c++) bb[c] = b2[tc * 4 + c];
#pragma unroll
            for (int r = 0; r < 8; r++) {
                float4 o;
                o.x = acc[r][0] + bb[0];
                o.y = acc[r][1] + bb[1];
                o.z = acc[r][2] + bb[2];
                o.w = acc[r][3] + bb[3];
                *(float4*)(g_h + (rowBase + tr * 8 + r) * DOUT + tc * 4) = o;
            }
        }
        __syncthreads();
    }
#endif
}

// ---------------------------------------------------------------------------
// Gather kernel: 16 lanes per (u,n) row, 8 floats (32B) per lane.
// g_h reads via 256-bit evict_last loads; up/out evict-first streaming.
// ---------------------------------------------------------------------------
__global__ __launch_bounds__(256)
void gather_add_kernel(const float* __restrict__ up,
                       const int*   __restrict__ idx,
                       float*       __restrict__ out)
{
    long t    = (long)blockIdx.x * blockDim.x + threadIdx.x;
    long row  = t >> 4;                 // (u*8 + n), < 524288
    int  lane = threadIdx.x & 15;       // 8-float chunk id
    int  n    = (int)(row & 7);

    const int* ip = idx + row * 3;
    int i0 = __ldg(ip + 0);
    int i1 = __ldg(ip + 1);
    int i2 = __ldg(ip + 2);

    const float* p0 = g_h + (size_t)(i0 * NNm + n) * DOUT + lane * 8;
    const float* p1 = g_h + (size_t)(i1 * NNm + n) * DOUT + lane * 8;
    const float* p2 = g_h + (size_t)(i2 * NNm + n) * DOUT + lane * 8;

    float a[8], b[8], c[8];
    ldg_evl8(p0, a);
    ldg_evl8(p1, b);
    ldg_evl8(p2, c);

    const float4* upp = (const float4*)(up + row * DOUT + lane * 8);
    float4 u0 = __ldcs(upp);
    float4 u1 = __ldcs(upp + 1);

    const float inv3 = 1.0f / 3.0f;
    float4 o0, o1;
    o0.x = fmaf(a[0] + b[0] + c[0], inv3, u0.x);
    o0.y = fmaf(a[1] + b[1] + c[1], inv3, u0.y);
    o0.z = fmaf(a[2] + b[2] + c[2], inv3, u0.z);
    o0.w = fmaf(a[3] + b[3] + c[3], inv3, u0.w);
    o1.x = fmaf(a[4] + b[4] + c[4], inv3, u1.x);
    o1.y = fmaf(a[5] + b[5] + c[5], inv3, u1.y);
    o1.z = fmaf(a[6] + b[6] + c[6], inv3, u1.z);
    o1.w = fmaf(a[7] + b[7] + c[7], inv3, u1.w);

    float4* op = (float4*)(out + row * DOUT + lane * 8);
    __stcs(op,     o0);
    __stcs(op + 1, o1);
}

// ---------------------------------------------------------------------------
// Launch: inputs = down_features, up_features, idx, W1, b1, W2, b2
// ---------------------------------------------------------------------------
extern "C" void kernel_launch(void* const* d_in, const int* in_sizes, int n_in,
                              void* d_out, int out_size)
{
    const float* down = (const float*)d_in[0];
    const float* up   = (const float*)d_in[1];
    const int*   idx  = (const int*)  d_in[2];
    const float* W1   = (const float*)d_in[3];
    const float* b1   = (const float*)d_in[4];
    const float* W2   = (const float*)d_in[5];
    const float* b2   = (const float*)d_in[6];
    float* out = (float*)d_out;

    static int smem_set = 0;
    if (!smem_set) {
        cudaFuncSetAttribute(mlp_kernel,
                             cudaFuncAttributeMaxDynamicSharedMemorySize, SMEM_TOTAL);
        smem_set = 1;
    }

    // 1. Split weights into bf16 hi/lo
    wsplit_kernel<<<192, 256>>>(W1, W2);

    // 2. MLP -> g_h (256 rows per CTA)
    mlp_kernel<<<M_ROWS / 256, 256, SMEM_TOTAL>>>(down, W1, b1, W2, b2);

    // 3. Gather + mean + add (16 lanes x 32B per row)
    gather_add_kernel<<<(int)(OUT_ROWS * 16 / 256), 256>>>(up, idx, out);
}

// round 7
// speedup vs baseline: 1.1249x; 1.1249x over previous
#include <cuda_runtime.h>
#include <cuda_bf16.h>
#include <cstdint>

// Problem constants
#define LDm   16384
#define LUm   65536
#define NNm   8
#define DIN   256
#define DOUT  128
#define M_ROWS (LDm * NNm)            // 131072 MLP rows
#define OUT_ROWS ((long)LUm * NNm)    // 524288 output rows

// Arch-specific (sm_103a/sm_100a) pass?
#if defined(__CUDA_ARCH__) && (defined(__CUDA_ARCH_FEAT_SM103_ALL) || \
    defined(__CUDA_ARCH_FEAT_SM100_ALL) || \
    (defined(__CUDA_ARCH_SPECIFIC__) && (__CUDA_ARCH_SPECIFIC__ >= 1000)))
#define HAS_TCGEN05 1
#else
#define HAS_TCGEN05 0
#endif

// Scratch: h = relu(x@W1+b1)@W2+b2  [LD, N, D_OUT] (64 MB)
__device__ __align__(128) float g_h[(size_t)M_ROWS * DOUT];
// Precomputed bf16 hi/lo splits of W1^T, W2^T (B operands, N x K, K-major)
__device__ __align__(16) __nv_bfloat16 g_w1t_hi[DOUT * DIN];
__device__ __align__(16) __nv_bfloat16 g_w1t_lo[DOUT * DIN];
__device__ __align__(16) __nv_bfloat16 g_w2t_hi[DOUT * DOUT];
__device__ __align__(16) __nv_bfloat16 g_w2t_lo[DOUT * DOUT];

#define SMEM_TOTAL 67584

// ---------------------------------------------------------------------------
// Pre-kernel: split W1^T / W2^T into bf16 hi/lo
// ---------------------------------------------------------------------------
__global__ void wsplit_kernel(const float* __restrict__ W1,
                              const float* __restrict__ W2)
{
    int t = blockIdx.x * blockDim.x + threadIdx.x;
    if (t < DOUT * DIN) {                   // W1^T: [n][k], n<128, k<256
        int n = t >> 8, k = t & 255;
        float x = W1[k * DOUT + n];
        uint32_t b = __float_as_uint(x);
        float hf = __uint_as_float(b & 0xFFFF0000u);
        g_w1t_hi[t] = __ushort_as_bfloat16((unsigned short)(b >> 16));
        g_w1t_lo[t] = __float2bfloat16(x - hf);
    } else {
        int t2 = t - DOUT * DIN;
        if (t2 < DOUT * DOUT) {             // W2^T: [n][k], n<128, k<128
            int n = t2 >> 7, k = t2 & 127;
            float x = W2[k * DOUT + n];
            uint32_t b = __float_as_uint(x);
            float hf = __uint_as_float(b & 0xFFFF0000u);
            g_w2t_hi[t2] = __ushort_as_bfloat16((unsigned short)(b >> 16));
            g_w2t_lo[t2] = __float2bfloat16(x - hf);
        }
    }
}

#if HAS_TCGEN05
// ---------------------------------------------------------------------------
// PTX helpers (sm_103a tcgen05 / mbarrier) — only in the arch-specific pass
// ---------------------------------------------------------------------------
__device__ __forceinline__ uint32_t smem_u32(const void* p) {
    uint32_t a;
    asm("{ .reg .u64 t; cvta.to.shared.u64 t, %1; cvt.u32.u64 %0, t; }"
        : "=r"(a) : "l"(p));
    return a;
}
__device__ __forceinline__ uint32_t elect_one() {
    uint32_t p;
    asm volatile("{ .reg .pred p; elect.sync _|p, 0xFFFFFFFF; selp.b32 %0,1,0,p; }"
                 : "=r"(p));
    return p;
}
#define TCG_ALLOC(sm, n)  asm volatile("tcgen05.alloc.cta_group::1.sync.aligned.shared::cta.b32 [%0], %1;" :: "r"(sm), "r"((uint32_t)(n)) : "memory")
#define TCG_DEALLOC(t, n) asm volatile("tcgen05.dealloc.cta_group::1.sync.aligned.b32 %0, %1;" :: "r"(t), "r"((uint32_t)(n)))
#define TCG_RELINQ()      asm volatile("tcgen05.relinquish_alloc_permit.cta_group::1.sync.aligned;")
#define TCG_COMMIT(mb)    asm volatile("tcgen05.commit.cta_group::1.mbarrier::arrive::one.shared::cluster.b64 [%0];" :: "r"(mb) : "memory")
#define TCG_WAIT_LD()     asm volatile("tcgen05.wait::ld.sync.aligned;" ::: "memory")
#define TCG_FENCE_BEFORE() asm volatile("tcgen05.fence::before_thread_sync;" ::: "memory")
#define TCG_FENCE_AFTER()  asm volatile("tcgen05.fence::after_thread_sync;" ::: "memory")
#define FENCE_ASYNC_SHARED() asm volatile("fence.proxy.async.shared::cta;" ::: "memory")
#define MBAR_INIT(mb, c)  asm volatile("mbarrier.init.shared.b64 [%0], %1;" :: "r"(mb), "r"((uint32_t)(c)) : "memory")
#define MBAR_INVAL(mb)    asm volatile("mbarrier.inval.shared.b64 [%0];" :: "r"(mb) : "memory")

__device__ __forceinline__ void mbar_wait(uint32_t mb, uint32_t parity) {
    asm volatile(
        "{\n\t.reg .pred P1;\n\t"
        "WAIT_LOOP_%=:\n\t"
        "mbarrier.try_wait.parity.acquire.cta.shared::cta.b64 P1, [%0], %1, 0x989680;\n\t"
        "@P1 bra.uni WAIT_DONE_%=;\n\t"
        "bra.uni WAIT_LOOP_%=;\n\t"
        "WAIT_DONE_%=:\n\t}"
        :: "r"(mb), "r"(parity) : "memory");
}

__device__ __forceinline__ void mma_ss(uint32_t d, uint64_t ad, uint64_t bd,
                                       uint32_t idesc, uint32_t en) {
    asm volatile(
        "{\n\t.reg .pred p;\n\tsetp.ne.u32 p, %4, 0;\n\t"
        "tcgen05.mma.cta_group::1.kind::f16 [%0], %1, %2, %3, {%5,%5,%5,%5}, p;\n\t}"
        :: "r"(d), "l"(ad), "l"(bd), "r"(idesc), "r"(en), "r"(0u) : "memory");
}

#define LDTM_X16(r, a) \
    asm volatile("tcgen05.ld.sync.aligned.32x32b.x16.b32 " \
        "{%0,%1,%2,%3,%4,%5,%6,%7,%8,%9,%10,%11,%12,%13,%14,%15}, [%16];" \
        : "=r"((r)[0]),"=r"((r)[1]),"=r"((r)[2]),"=r"((r)[3]), \
          "=r"((r)[4]),"=r"((r)[5]),"=r"((r)[6]),"=r"((r)[7]), \
          "=r"((r)[8]),"=r"((r)[9]),"=r"((r)[10]),"=r"((r)[11]), \
          "=r"((r)[12]),"=r"((r)[13]),"=r"((r)[14]),"=r"((r)[15]) : "r"(a))

#define LDTM_X32(r, a) \
    asm volatile("tcgen05.ld.sync.aligned.32x32b.x32.b32 " \
        "{%0,%1,%2,%3,%4,%5,%6,%7,%8,%9,%10,%11,%12,%13,%14,%15," \
        "%16,%17,%18,%19,%20,%21,%22,%23,%24,%25,%26,%27,%28,%29,%30,%31}, [%32];" \
        : "=r"((r)[0]),"=r"((r)[1]),"=r"((r)[2]),"=r"((r)[3]), \
          "=r"((r)[4]),"=r"((r)[5]),"=r"((r)[6]),"=r"((r)[7]), \
          "=r"((r)[8]),"=r"((r)[9]),"=r"((r)[10]),"=r"((r)[11]), \
          "=r"((r)[12]),"=r"((r)[13]),"=r"((r)[14]),"=r"((r)[15]), \
          "=r"((r)[16]),"=r"((r)[17]),"=r"((r)[18]),"=r"((r)[19]), \
          "=r"((r)[20]),"=r"((r)[21]),"=r"((r)[22]),"=r"((r)[23]), \
          "=r"((r)[24]),"=r"((r)[25]),"=r"((r)[26]),"=r"((r)[27]), \
          "=r"((r)[28]),"=r"((r)[29]),"=r"((r)[30]),"=r"((r)[31]) : "r"(a))

__device__ __forceinline__ uint64_t mk_desc(uint32_t addr) {
    return ((uint64_t)2 << 61) | ((uint64_t)1 << 46) | ((uint64_t)64 << 32) |
           ((uint64_t)1 << 16) | (uint64_t)((addr >> 4) & 0x3FFF);
}
#endif // HAS_TCGEN05

#define SWZ(o) ((o) ^ (((o) >> 3) & 0x70))

// Truncation split: hi = top-16-bits of fp32, lo = rn_bf16(x - hi)
__device__ __forceinline__ void split2(float x0, float x1, uint32_t& hi, uint32_t& lo) {
    uint32_t b0 = __float_as_uint(x0), b1 = __float_as_uint(x1);
    hi = __byte_perm(b0, b1, 0x7632);
    float l0 = x0 - __uint_as_float(b0 & 0xFFFF0000u);
    float l1 = x1 - __uint_as_float(b1 & 0xFFFF0000u);
    asm("cvt.rn.bf16x2.f32 %0, %1, %2;" : "=r"(lo) : "f"(l1), "f"(l0));
}

// 256-bit evict_last global load (8 floats) — evict_last requires 256-bit width
__device__ __forceinline__ void ldg_evl8(const float* p, float* v) {
    uint64_t a, b, c, d;
    asm volatile("ld.global.nc.L2::evict_last.v4.b64 {%0,%1,%2,%3}, [%4];"
        : "=l"(a), "=l"(b), "=l"(c), "=l"(d) : "l"(p));
    v[0] = __uint_as_float((uint32_t)a); v[1] = __uint_as_float((uint32_t)(a >> 32));
    v[2] = __uint_as_float((uint32_t)b); v[3] = __uint_as_float((uint32_t)(b >> 32));
    v[4] = __uint_as_float((uint32_t)c); v[5] = __uint_as_float((uint32_t)(c >> 32));
    v[6] = __uint_as_float((uint32_t)d); v[7] = __uint_as_float((uint32_t)(d >> 32));
}

// SMEM region offsets (tcgen05 path) — R3 layout
#define SM_AHI 1024
#define SM_ALO 17408
#define SM_BHI 33792
#define SM_BLO 50176
#define SM_B1  66560
#define SM_B2  67072

// ---------------------------------------------------------------------------
// MLP kernel — EXACT R3 version (measured 71us): 128 rows/CTA, grid 1024.
// ---------------------------------------------------------------------------
__global__ __launch_bounds__(256, 2)
void mlp_kernel(const float* __restrict__ X,
                const float* __restrict__ W1,
                const float* __restrict__ b1,
                const float* __restrict__ W2,
                const float* __restrict__ b2)
{
    extern __shared__ char smem[];
#if HAS_TCGEN05
    const uint32_t sb  = smem_u32(smem);
    const int tid = threadIdx.x, wid = tid >> 5, lid = tid & 31;
    const long rowBase = (long)blockIdx.x * 128;

    float* b1s = (float*)(smem + SM_B1);
    float* b2s = (float*)(smem + SM_B2);

    if (wid == 0) { TCG_ALLOC(sb + 0, 256); TCG_RELINQ(); }
    if (tid == 0) MBAR_INIT(sb + 8, 1);
    if (tid < 128) { b1s[tid] = b1[tid]; b2s[tid] = b2[tid]; }
    __syncthreads();

    uint32_t tmem;
    asm volatile("ld.shared.b32 %0, [%1];" : "=r"(tmem) : "r"(sb + 0));

    const uint32_t idesc = (1u << 4) | (1u << 7) | (1u << 10) |
                           ((DOUT / 8) << 17) | ((128 / 16) << 24);
    const uint64_t adhi = mk_desc(sb + SM_AHI);
    const uint64_t adlo = mk_desc(sb + SM_ALO);
    const uint64_t bdhi = mk_desc(sb + SM_BHI);
    const uint64_t bdlo = mk_desc(sb + SM_BLO);

    uint32_t parity = 0;

    // ================= GEMM1: 4 K-chunks of 64 =================
    for (int kb = 0; kb < 4; kb++) {
        const float* Xc = X + rowBase * DIN + kb * 64;
#pragma unroll
        for (int it = 0; it < 4; it++) {
            int f  = it * 256 + tid;
            int r  = f >> 3;
            int c8 = f & 7;
            const float4* src = (const float4*)(Xc + (size_t)r * DIN + c8 * 8);
            float4 va = src[0], vb = src[1];
            uint32_t h0, l0, h1, l1, h2, l2, h3, l3;
            split2(va.x, va.y, h0, l0);
            split2(va.z, va.w, h1, l1);
            split2(vb.x, vb.y, h2, l2);
            split2(vb.z, vb.w, h3, l3);
            uint32_t off = SWZ((uint32_t)(r * 128 + c8 * 16));
            *(uint4*)(smem + SM_AHI + off) = make_uint4(h0, h1, h2, h3);
            *(uint4*)(smem + SM_ALO + off) = make_uint4(l0, l1, l2, l3);
        }
#pragma unroll
        for (int it = 0; it < 8; it++) {
            int f = it * 256 + tid;
            int g = f & 1023;
            int n = g >> 3, c16 = g & 7;
            const __nv_bfloat16* wsrc = (f < 1024) ? g_w1t_hi : g_w1t_lo;
            uint4 v = *(const uint4*)(wsrc + (size_t)n * DIN + kb * 64 + c16 * 8);
            uint32_t dst = ((f < 1024) ? SM_BHI : SM_BLO) + SWZ((uint32_t)(n * 128 + c16 * 16));
            *(uint4*)(smem + dst) = v;
        }
        __syncthreads();

        if (wid == 0) {
            FENCE_ASYNC_SHARED();
            if (elect_one()) {
#pragma unroll
                for (int ks = 0; ks < 4; ks++)
                    mma_ss(tmem, adhi + ks * 2, bdhi + ks * 2, idesc, (kb > 0) || (ks > 0));
#pragma unroll
                for (int ks = 0; ks < 4; ks++)
                    mma_ss(tmem, adhi + ks * 2, bdlo + ks * 2, idesc, 1);
#pragma unroll
                for (int ks = 0; ks < 4; ks++)
                    mma_ss(tmem, adlo + ks * 2, bdhi + ks * 2, idesc, 1);
                TCG_COMMIT(sb + 8);
            }
        }
        mbar_wait(sb + 8, parity); parity ^= 1;
        TCG_FENCE_AFTER();
        __syncthreads();
    }

    // ================= GEMM2: 2 K-chunks of 64 =================
    for (int c2 = 0; c2 < 2; c2++) {
        if (wid < 4) {
            int row = wid * 32 + lid;
#pragma unroll
            for (int part = 0; part < 4; part++) {
                uint32_t r16[16];
                LDTM_X16(r16, tmem + c2 * 64 + part * 16);
                TCG_WAIT_LD();
#pragma unroll
                for (int grp = 0; grp < 2; grp++) {
                    uint32_t hs[4], ls[4];
#pragma unroll
                    for (int q = 0; q < 4; q++) {
                        int c = grp * 8 + q * 2;
                        float x0 = __uint_as_float(r16[c])     + b1s[c2 * 64 + part * 16 + c];
                        float x1 = __uint_as_float(r16[c + 1]) + b1s[c2 * 64 + part * 16 + c + 1];
                        x0 = fmaxf(x0, 0.f);
                        x1 = fmaxf(x1, 0.f);
                        split2(x0, x1, hs[q], ls[q]);
                    }
                    uint32_t off = SWZ((uint32_t)(row * 128 + (part * 16 + grp * 8) * 2));
                    *(uint4*)(smem + SM_AHI + off) = make_uint4(hs[0], hs[1], hs[2], hs[3]);
                    *(uint4*)(smem + SM_ALO + off) = make_uint4(ls[0], ls[1], ls[2], ls[3]);
                }
            }
        } else {
            int t2 = tid - 128;
#pragma unroll
            for (int it = 0; it < 16; it++) {
                int f = it * 128 + t2;
                int g = f & 1023;
                int n = g >> 3, c16 = g & 7;
                const __nv_bfloat16* wsrc = (f < 1024) ? g_w2t_hi : g_w2t_lo;
                uint4 v = *(const uint4*)(wsrc + (size_t)n * DOUT + c2 * 64 + c16 * 8);
                uint32_t dst = ((f < 1024) ? SM_BHI : SM_BLO) + SWZ((uint32_t)(n * 128 + c16 * 16));
                *(uint4*)(smem + dst) = v;
            }
        }
        __syncthreads();

        if (wid == 0) {
            FENCE_ASYNC_SHARED();
            if (elect_one()) {
#pragma unroll
                for (int ks = 0; ks < 4; ks++)
                    mma_ss(tmem + 128, adhi + ks * 2, bdhi + ks * 2, idesc, (c2 > 0) || (ks > 0));
#pragma unroll
                for (int ks = 0; ks < 4; ks++)
                    mma_ss(tmem + 128, adhi + ks * 2, bdlo + ks * 2, idesc, 1);
#pragma unroll
                for (int ks = 0; ks < 4; ks++)
                    mma_ss(tmem + 128, adlo + ks * 2, bdhi + ks * 2, idesc, 1);
                TCG_COMMIT(sb + 8);
            }
        }
        mbar_wait(sb + 8, parity); parity ^= 1;
        TCG_FENCE_AFTER();
        __syncthreads();
    }

    // ================= Epilogue: D2 + b2 -> g_h =================
    if (wid < 4) {
        int row = wid * 32 + lid;
        float* dst = g_h + (size_t)(rowBase + row) * DOUT;
#pragma unroll
        for (int grp = 0; grp < 4; grp++) {
            uint32_t r32[32];
            LDTM_X32(r32, tmem + 128 + grp * 32);
            TCG_WAIT_LD();
#pragma unroll
            for (int cb = 0; cb < 8; cb++) {
                float4 o;
                o.x = __uint_as_float(r32[cb * 4 + 0]) + b2s[grp * 32 + cb * 4 + 0];
                o.y = __uint_as_float(r32[cb * 4 + 1]) + b2s[grp * 32 + cb * 4 + 1];
                o.z = __uint_as_float(r32[cb * 4 + 2]) + b2s[grp * 32 + cb * 4 + 2];
                o.w = __uint_as_float(r32[cb * 4 + 3]) + b2s[grp * 32 + cb * 4 + 3];
                *(float4*)(dst + grp * 32 + cb * 4) = o;
            }
        }
        TCG_FENCE_BEFORE();
    }
    __syncthreads();
    if (tid == 0) MBAR_INVAL(sb + 8);
    __syncthreads();
    if (wid == 0) TCG_DEALLOC(tmem, 256);

#else  // ===================== fp32 FFMA fallback =====================
    float (*xs)[68]   = (float (*)[68])(smem);
    float (*ws)[128]  = (float (*)[128])(smem + 32 * 68 * 4);
    float (*h1T)[68]  = (float (*)[68])(smem + 32 * 68 * 4 + 32 * 128 * 4);

    const int tid = threadIdx.x;
    const int tr  = tid >> 5;
    const int tc  = tid & 31;

    for (int half = 0; half < 2; half++) {
        const long rowBase = (long)blockIdx.x * 128 + half * 64;
        float acc[8][4];
#pragma unroll
        for (int r = 0; r < 8; r++)
#pragma unroll
            for (int c = 0; c < 4; c++) acc[r][c] = 0.f;

        for (int kb = 0; kb < DIN; kb += 32) {
#pragma unroll
            for (int it = 0; it < 2; it++) {
                int f = tid + it * 256;
                int r  = f >> 3;
                int k4 = f & 7;
                float4 v = *(const float4*)(X + (rowBase + r) * DIN + kb + k4 * 4);
                xs[k4 * 4 + 0][r] = v.x;
                xs[k4 * 4 + 1][r] = v.y;
                xs[k4 * 4 + 2][r] = v.z;
                xs[k4 * 4 + 3][r] = v.w;
            }
#pragma unroll
            for (int it = 0; it < 4; it++) {
                int f  = tid + it * 256;
                int kr = f >> 5;
                int c4 = f & 31;
                *(float4*)&ws[kr][c4 * 4] =
                    *(const float4*)(W1 + (size_t)(kb + kr) * DOUT + c4 * 4);
            }
            __syncthreads();
#pragma unroll
            for (int kk = 0; kk < 32; kk++) {
                float4 xa = *(float4*)&xs[kk][tr * 8];
                float4 xb = *(float4*)&xs[kk][tr * 8 + 4];
                float4 w  = *(float4*)&ws[kk][tc * 4];
                float xr[8] = {xa.x, xa.y, xa.z, xa.w, xb.x, xb.y, xb.z, xb.w};
                float wr[4] = {w.x, w.y, w.z, w.w};
#pragma unroll
                for (int r = 0; r < 8; r++)
#pragma unroll
                    for (int c = 0; c < 4; c++)
                        acc[r][c] = fmaf(xr[r], wr[c], acc[r][c]);
            }
            __syncthreads();
        }
        {
            float bb[4];
#pragma unroll
            for (int c = 0; c < 4; c++) bb[c] = b1[tc * 4 + c];
#pragma unroll
            for (int r = 0; r < 8; r++)
#pragma unroll
                for (int c = 0; c < 4; c++) {
                    float v = acc[r][c] + bb[c];
                    h1T[tc * 4 + c][tr * 8 + r] = fmaxf(v, 0.f);
                    acc[r][c] = 0.f;
                }
        }
        __syncthreads();

        for (int kb = 0; kb < DOUT; kb += 32) {
#pragma unroll
            for (int it = 0; it < 4; it++) {
                int f  = tid + it * 256;
                int kr = f >> 5;
                int c4 = f & 31;
                *(float4*)&ws[kr][c4 * 4] =
                    *(const float4*)(W2 + (size_t)(kb + kr) * DOUT + c4 * 4);
            }
            __syncthreads();
#pragma unroll
            for (int kk = 0; kk < 32; kk++) {
                float4 xa = *(float4*)&h1T[kb + kk][tr * 8];
                float4 xb = *(float4*)&h1T[kb + kk][tr * 8 + 4];
                float4 w  = *(float4*)&ws[kk][tc * 4];
                float xr[8] = {xa.x, xa.y, xa.z, xa.w, xb.x, xb.y, xb.z, xb.w};
                float wr[4] = {w.x, w.y, w.z, w.w};
#pragma unroll
                for (int r = 0; r < 8; r++)
#pragma unroll
                    for (int c = 0; c < 4; c++)
                        acc[r][c] = fmaf(xr[r], wr[c], acc[r][c]);
            }
            __syncthreads();
        }
        {
            float bb[4];
#pragma unroll
            for (int c = 0; c < 4; c++) bb[c] = b2[tc * 4 + c];
#pragma unroll
            for (int r = 0; r < 8; r++) {
                float4 o;
                o.x = acc[r][0] + bb[0];
                o.y = acc[r][1] + bb[1];
                o.z = acc[r][2] + bb[2];
                o.w = acc[r][3] + bb[3];
                *(float4*)(g_h + (rowBase + tr * 8 + r) * DOUT + tc * 4) = o;
            }
        }
        __syncthreads();
    }
#endif
}

// ---------------------------------------------------------------------------
// Gather kernel: 16 lanes per (u,n) row, 8 floats (32B) per lane.
// g_h reads via 256-bit evict_last loads; up/out evict-first streaming.
// ---------------------------------------------------------------------------
__global__ __launch_bounds__(256)
void gather_add_kernel(const float* __restrict__ up,
                       const int*   __restrict__ idx,
                       float*       __restrict__ out)
{
    long t    = (long)blockIdx.x * blockDim.x + threadIdx.x;
    long row  = t >> 4;                 // (u*8 + n), < 524288
    int  lane = threadIdx.x & 15;       // 8-float chunk id
    int  n    = (int)(row & 7);

    const int* ip = idx + row * 3;
    int i0 = __ldg(ip + 0);
    int i1 = __ldg(ip + 1);
    int i2 = __ldg(ip + 2);

    const float* p0 = g_h + (size_t)(i0 * NNm + n) * DOUT + lane * 8;
    const float* p1 = g_h + (size_t)(i1 * NNm + n) * DOUT + lane * 8;
    const float* p2 = g_h + (size_t)(i2 * NNm + n) * DOUT + lane * 8;

    float a[8], b[8], c[8];
    ldg_evl8(p0, a);
    ldg_evl8(p1, b);
    ldg_evl8(p2, c);

    const float4* upp = (const float4*)(up + row * DOUT + lane * 8);
    float4 u0 = __ldcs(upp);
    float4 u1 = __ldcs(upp + 1);

    const float inv3 = 1.0f / 3.0f;
    float4 o0, o1;
    o0.x = fmaf(a[0] + b[0] + c[0], inv3, u0.x);
    o0.y = fmaf(a[1] + b[1] + c[1], inv3, u0.y);
    o0.z = fmaf(a[2] + b[2] + c[2], inv3, u0.z);
    o0.w = fmaf(a[3] + b[3] + c[3], inv3, u0.w);
    o1.x = fmaf(a[4] + b[4] + c[4], inv3, u1.x);
    o1.y = fmaf(a[5] + b[5] + c[5], inv3, u1.y);
    o1.z = fmaf(a[6] + b[6] + c[6], inv3, u1.z);
    o1.w = fmaf(a[7] + b[7] + c[7], inv3, u1.w);

    float4* op = (float4*)(out + row * DOUT + lane * 8);
    __stcs(op,     o0);
    __stcs(op + 1, o1);
}

// ---------------------------------------------------------------------------
// Launch: inputs = down_features, up_features, idx, W1, b1, W2, b2
// ---------------------------------------------------------------------------
extern "C" void kernel_launch(void* const* d_in, const int* in_sizes, int n_in,
                              void* d_out, int out_size)
{
    const float* down = (const float*)d_in[0];
    const float* up   = (const float*)d_in[1];
    const int*   idx  = (const int*)  d_in[2];
    const float* W1   = (const float*)d_in[3];
    const float* b1   = (const float*)d_in[4];
    const float* W2   = (const float*)d_in[5];
    const float* b2   = (const float*)d_in[6];
    float* out = (float*)d_out;

    static int smem_set = 0;
    if (!smem_set) {
        cudaFuncSetAttribute(mlp_kernel,
                             cudaFuncAttributeMaxDynamicSharedMemorySize, SMEM_TOTAL);
        smem_set = 1;
    }

    // 1. Split weights into bf16 hi/lo
    wsplit_kernel<<<192, 256>>>(W1, W2);

    // 2. MLP -> g_h (R3 shape: 128 rows per CTA, grid 1024)
    mlp_kernel<<<M_ROWS / 128, 256, SMEM_TOTAL>>>(down, W1, b1, W2, b2);

    // 3. Gather + mean + add (16 lanes x 32B per row, evict_last g_h reads)
    gather_add_kernel<<<(int)(OUT_ROWS * 16 / 256), 256>>>(up, idx, out);
}